// round 6
// baseline (speedup 1.0000x reference)
#include <cuda_runtime.h>
#include <cuda_fp16.h>

// ---------------------------------------------------------------------------
// ConvDiffLogicMNIST — difflogic CNN forward.
// Gate algebra: out = A + B*a + C*b + D*a*b (per-gate coefs from softmax(w)).
// Pipeline: coef prep -> conv mega (block/image, smem) -> batch-major fc x3
//           -> groupsum. FC layers use [gate][batch] layout: metadata uniform
//           per warp, activation reads/writes fully coalesced, L2-resident.
// ---------------------------------------------------------------------------

#define DEV_INLINE __device__ __forceinline__

static constexpr int NT  = 512;   // conv mega block size
static constexpr int BMX = 128;   // max batch supported by scratch layout

// ---- conv coefficient table offsets (float4 units) ----
static constexpr int OFF_C1_0 = 0;       // 16*4
static constexpr int OFF_C1_1 = 64;      // 16*2
static constexpr int OFF_C1_2 = 96;      // 16*1
static constexpr int OFF_C2_0 = 112;     // 48*4
static constexpr int OFF_C2_1 = 304;     // 48*2
static constexpr int OFF_C2_2 = 400;     // 48*1
static constexpr int OFF_C3_0 = 448;     // 144*4
static constexpr int OFF_C3_1 = 1024;    // 144*2
static constexpr int OFF_C3_2 = 1312;    // 144*1
static constexpr int N_CONV_COEF = 1456;

// ---- fc gate offsets (gate units) ----
static constexpr int FC1_OFF = 0;        // 20480
static constexpr int FC2_OFF = 20480;    // 10240
static constexpr int FC3_OFF = 30720;    // 5120
static constexpr int N_FC    = 35840;
static constexpr int N_GATES = 37296;

// ---- fc gate metadata: one 16B record -> single broadcast LDG.128 ----
struct __align__(16) FcGate {
    unsigned idx;     // ia | ib<<16
    __half2  ab;      // (A, B)
    __half2  cd;      // (C, D)
    unsigned pad;
};

// ---- device scratch (batch-major activations) ----
__device__ float4 g_coef[N_CONV_COEF];
__device__ FcGate g_fcg[N_FC];
__device__ float  g_act3T[1296 * BMX];
__device__ float  g_fc1T[20480 * BMX];
__device__ float  g_fc2T[10240 * BMX];
__device__ float  g_fc3T[5120 * BMX];

// op -> (const, a, b, ab) coefficients for the 16 two-input soft boolean ops
__constant__ float OPC0[16]  = {0,0,0,0, 0,0,0,0, 1,1,1,1, 1,1,1,1};
__constant__ float OPCA[16]  = {0,0,1,1, 0,0,1,1, -1,-1,0,0, -1,-1,0,0};
__constant__ float OPCB[16]  = {0,0,0,0, 1,1,1,1, -1,-1,-1,-1, 0,0,0,0};
__constant__ float OPCAB[16] = {0,1,-1,0, -1,0,-2,-1, 1,2,0,1, 0,1,-1,0};

DEV_INLINE float gate_eval(float A, float Bc, float Cc, float D, float a, float b) {
    return fmaf(b, fmaf(a, D, Cc), fmaf(a, Bc, A));
}
DEV_INLINE float gate_eval4(float4 c, float a, float b) {
    return gate_eval(c.x, c.y, c.z, c.w, a, b);
}
DEV_INLINE float sel4(const float h[4], int i) {
    float r = h[0];
    r = (i == 1) ? h[1] : r;
    r = (i == 2) ? h[2] : r;
    r = (i == 3) ? h[3] : r;
    return r;
}

// ---------------------------------------------------------------------------
// Kernel 1: softmax(w) -> (A,B,C,D); conv -> g_coef fp32; fc -> 16B records.
// ---------------------------------------------------------------------------
struct CoefSeg { const float* w; const int* idx; int off; int cnt; };
struct CoefArgs { CoefSeg s[12]; };

__global__ void coef_kernel(CoefArgs args) {
    int tid = blockIdx.x * blockDim.x + threadIdx.x;
    if (tid >= N_GATES) return;
    int rem = tid, i = 0;
    while (rem >= args.s[i].cnt) { rem -= args.s[i].cnt; i++; }
    const float* w = args.s[i].w + rem * 16;

    float wv[16], m = -1e30f;
#pragma unroll
    for (int k = 0; k < 16; k++) { wv[k] = w[k]; m = fmaxf(m, wv[k]); }
    float e[16], sum = 0.f;
#pragma unroll
    for (int k = 0; k < 16; k++) { e[k] = __expf(wv[k] - m); sum += e[k]; }
    float inv = 1.f / sum;
    float A = 0.f, Bc = 0.f, Cc = 0.f, D = 0.f;
#pragma unroll
    for (int k = 0; k < 16; k++) {
        float p = e[k] * inv;
        A  = fmaf(p, OPC0[k],  A);
        Bc = fmaf(p, OPCA[k],  Bc);
        Cc = fmaf(p, OPCB[k],  Cc);
        D  = fmaf(p, OPCAB[k], D);
    }
    if (i < 9) {
        g_coef[args.s[i].off + rem] = make_float4(A, Bc, Cc, D);
    } else {
        int o = args.s[i].off + rem;
        const int* idx = args.s[i].idx;
        FcGate gte;
        gte.idx = (unsigned)idx[rem] | ((unsigned)idx[args.s[i].cnt + rem] << 16);
        gte.ab  = __floats2half2_rn(A, Bc);
        gte.cd  = __floats2half2_rn(Cc, D);
        gte.pad = 0;
        g_fcg[o] = gte;
    }
}

// ---------------------------------------------------------------------------
// Conv phase (device): logic-tree conv + 2x2 maxpool, smem in -> smem out.
// Wiring decoded once per block into smem (wire: 9 ints per filter).
// ---------------------------------------------------------------------------
template <int CIN, int HIN, int KS, int PAD, int F, int OFF>
DEV_INLINE void conv_phase(const float* __restrict__ in_s, float* __restrict__ out_s,
                           const int* __restrict__ idx0, const int* __restrict__ idx1,
                           const int* __restrict__ idx2, int* __restrict__ wire,
                           int tid) {
    constexpr int OH  = HIN + 2 * PAD - KS + 1;
    constexpr int OHP = OH / 2;
    constexpr int NOUT = F * OHP * OHP;

    for (int f = tid; f < F; f += NT) {
        int sel = 0;
#pragma unroll
        for (int g = 0; g < 2; g++) {
            sel |= (idx1[f * 2 + g] & 3) << (g * 2);
            sel |= (idx1[F * 2 + f * 2 + g] & 3) << (4 + g * 2);
        }
        sel |= (idx2[f] & 1) << 8;
        sel |= (idx2[F + f] & 1) << 9;
        wire[f * 9 + 8] = sel;
#pragma unroll
        for (int j = 0; j < 8; j++) {
            int p = (j < 4) ? idx0[f * 4 + j] : idx0[F * 4 + f * 4 + (j - 4)];
            int c = p / (KS * KS);
            int kk = p % (KS * KS);
            wire[f * 9 + j] = (c << 8) | ((kk / KS) << 4) | (kk % KS);
        }
    }
    __syncthreads();

    for (int out = tid; out < NOUT; out += NT) {
        int px = out % OHP;
        int py = (out / OHP) % OHP;
        int f  = out / (OHP * OHP);

        int pk[8];
#pragma unroll
        for (int j = 0; j < 8; j++) pk[j] = wire[f * 9 + j];
        int sel = wire[f * 9 + 8];

        float4 c0[4], c1[2], c2;
#pragma unroll
        for (int g = 0; g < 4; g++) c0[g] = g_coef[OFF + f * 4 + g];
#pragma unroll
        for (int g = 0; g < 2; g++) c1[g] = g_coef[OFF + F * 4 + f * 2 + g];
        c2 = g_coef[OFF + F * 6 + f];

        float m = -1e30f;
#pragma unroll
        for (int dy = 0; dy < 2; dy++) {
#pragma unroll
            for (int dx = 0; dx < 2; dx++) {
                int y = 2 * py + dy, x = 2 * px + dx;
                float v[8];
#pragma unroll
                for (int j = 0; j < 8; j++) {
                    int iy = y + ((pk[j] >> 4) & 15) - PAD;
                    int ix = x + (pk[j] & 15) - PAD;
                    float t = 0.f;
                    if (PAD == 0 ||
                        ((unsigned)iy < (unsigned)HIN && (unsigned)ix < (unsigned)HIN))
                        t = in_s[(pk[j] >> 8) * HIN * HIN + iy * HIN + ix];
                    v[j] = t;
                }
                float h0[4];
#pragma unroll
                for (int g = 0; g < 4; g++) h0[g] = gate_eval4(c0[g], v[g], v[g + 4]);
                float h1[2];
                h1[0] = gate_eval4(c1[0], sel4(h0, sel & 3), sel4(h0, (sel >> 4) & 3));
                h1[1] = gate_eval4(c1[1], sel4(h0, (sel >> 2) & 3), sel4(h0, (sel >> 6) & 3));
                float ha = ((sel >> 8) & 1) ? h1[1] : h1[0];
                float hb = ((sel >> 9) & 1) ? h1[1] : h1[0];
                float o = gate_eval4(c2, ha, hb);
                m = fmaxf(m, o);
            }
        }
        out_s[out] = m;
    }
    __syncthreads();
}

// ---------------------------------------------------------------------------
// Kernel 2: conv mega — binarize + conv1..3 per image in smem (~25KB),
// final act3 written to global batch-major: g_act3T[idx*B + b].
// ---------------------------------------------------------------------------
struct ConvIdx {
    const int *c1_0, *c1_1, *c1_2;
    const int *c2_0, *c2_1, *c2_2;
    const int *c3_0, *c3_1, *c3_2;
};

__global__ __launch_bounds__(NT)
void conv_kernel(const float* __restrict__ x, ConvIdx ci, int B) {
    __shared__ float s_xbin[784];
    __shared__ float s_act1[2304];
    __shared__ float s_act2[1728];
    __shared__ float s_act3[1296];
    __shared__ int   s_wire[144 * 9];
    const int tid = threadIdx.x;
    const int b = blockIdx.x;

    for (int i = tid; i < 784; i += NT)
        s_xbin[i] = (x[b * 784 + i] > 0.5f) ? 1.f : 0.f;
    __syncthreads();

    conv_phase<1, 28, 5, 0, 16, OFF_C1_0>(s_xbin, s_act1, ci.c1_0, ci.c1_1, ci.c1_2, s_wire, tid);
    conv_phase<16, 12, 3, 1, 48, OFF_C2_0>(s_act1, s_act2, ci.c2_0, ci.c2_1, ci.c2_2, s_wire, tid);
    conv_phase<48, 6, 3, 1, 144, OFF_C3_0>(s_act2, s_act3, ci.c3_0, ci.c3_1, ci.c3_2, s_wire, tid);

    for (int i = tid; i < 1296; i += NT)
        g_act3T[i * B + b] = s_act3[i];
}

// ---------------------------------------------------------------------------
// Kernel 3: batch-major fc layer. Block = 4 gates x 128 batch lanes.
// Metadata uniform per gate-group (broadcast); activations coalesced.
// LAYER: 0 = act3T->fc1T, 1 = fc1T->fc2T, 2 = fc2T->fc3T.
// ---------------------------------------------------------------------------
template <int LAYER>
__global__ __launch_bounds__(512)
void fcb_kernel(int B) {
    constexpr int GOFF = (LAYER == 0) ? FC1_OFF : (LAYER == 1) ? FC2_OFF : FC3_OFF;
    const float* __restrict__ in =
        (LAYER == 0) ? g_act3T : (LAYER == 1) ? g_fc1T : g_fc2T;
    float* __restrict__ out =
        (LAYER == 0) ? g_fc1T : (LAYER == 1) ? g_fc2T : g_fc3T;

    const int bl = threadIdx.x & 127;
    const int gg = threadIdx.x >> 7;
    const int o  = blockIdx.x * 4 + gg;

    const uint4* __restrict__ meta = reinterpret_cast<const uint4*>(g_fcg);
    uint4 r = __ldg(&meta[GOFF + o]);
    if (bl >= B) return;
    float a  = in[(r.x & 0xffffu) * B + bl];
    float bb = in[(r.x >> 16) * B + bl];
    float2 AB = __half22float2(*reinterpret_cast<__half2*>(&r.y));
    float2 CD = __half22float2(*reinterpret_cast<__half2*>(&r.z));
    out[o * B + bl] = gate_eval(AB.x, AB.y, CD.x, CD.y, a, bb);
}

// ---------------------------------------------------------------------------
// Kernel 4: groupsum. Block per class w; 128 batch lanes x 4 gate groups.
// Every output written exactly once (no atomics, no zero-init needed).
// ---------------------------------------------------------------------------
__global__ __launch_bounds__(512)
void gsum_kernel(float* __restrict__ out, int B) {
    const int w  = blockIdx.x;       // 0..9
    const int bl = threadIdx.x & 127;
    const int gg = threadIdx.x >> 7; // 0..3
    __shared__ float part[4][128];

    float s = 0.f;
    if (bl < B) {
        const float* base = g_fc3T + (w * 512 + gg * 128) * B + bl;
#pragma unroll 8
        for (int k = 0; k < 128; k++) s += base[k * B];
    }
    part[gg][bl] = s;
    __syncthreads();
    if (gg == 0 && bl < B)
        out[bl * 10 + w] =
            (part[0][bl] + part[1][bl] + part[2][bl] + part[3][bl]) * (1.f / 30.f);
}

// ---------------------------------------------------------------------------
static inline int cdiv(int a, int b) { return (a + b - 1) / b; }

extern "C" void kernel_launch(void* const* d_in, const int* in_sizes, int n_in,
                              void* d_out, int out_size) {
    const float* x = (const float*)d_in[0];
    const int B = in_sizes[0] / (28 * 28);

    const int* c1_i0 = (const int*)d_in[1];
    const float* c1_w0 = (const float*)d_in[2];
    const int* c1_i1 = (const int*)d_in[3];
    const float* c1_w1 = (const float*)d_in[4];
    const int* c1_i2 = (const int*)d_in[5];
    const float* c1_w2 = (const float*)d_in[6];
    const int* c2_i0 = (const int*)d_in[7];
    const float* c2_w0 = (const float*)d_in[8];
    const int* c2_i1 = (const int*)d_in[9];
    const float* c2_w1 = (const float*)d_in[10];
    const int* c2_i2 = (const int*)d_in[11];
    const float* c2_w2 = (const float*)d_in[12];
    const int* c3_i0 = (const int*)d_in[13];
    const float* c3_w0 = (const float*)d_in[14];
    const int* c3_i1 = (const int*)d_in[15];
    const float* c3_w1 = (const float*)d_in[16];
    const int* c3_i2 = (const int*)d_in[17];
    const float* c3_w2 = (const float*)d_in[18];
    const int* fc1_i = (const int*)d_in[19];
    const float* fc1_w = (const float*)d_in[20];
    const int* fc2_i = (const int*)d_in[21];
    const float* fc2_w = (const float*)d_in[22];
    const int* fc3_i = (const int*)d_in[23];
    const float* fc3_w = (const float*)d_in[24];
    float* out = (float*)d_out;

    // 1) gate coefficients + fc metadata packing
    CoefArgs ca;
    ca.s[0]  = {c1_w0, nullptr, OFF_C1_0, 64};
    ca.s[1]  = {c1_w1, nullptr, OFF_C1_1, 32};
    ca.s[2]  = {c1_w2, nullptr, OFF_C1_2, 16};
    ca.s[3]  = {c2_w0, nullptr, OFF_C2_0, 192};
    ca.s[4]  = {c2_w1, nullptr, OFF_C2_1, 96};
    ca.s[5]  = {c2_w2, nullptr, OFF_C2_2, 48};
    ca.s[6]  = {c3_w0, nullptr, OFF_C3_0, 576};
    ca.s[7]  = {c3_w1, nullptr, OFF_C3_1, 288};
    ca.s[8]  = {c3_w2, nullptr, OFF_C3_2, 144};
    ca.s[9]  = {fc1_w, fc1_i, FC1_OFF, 20480};
    ca.s[10] = {fc2_w, fc2_i, FC2_OFF, 10240};
    ca.s[11] = {fc3_w, fc3_i, FC3_OFF, 5120};
    coef_kernel<<<cdiv(N_GATES, 256), 256>>>(ca);

    // 2) conv stack (block per image, smem-resident)
    ConvIdx ci{c1_i0, c1_i1, c1_i2, c2_i0, c2_i1, c2_i2, c3_i0, c3_i1, c3_i2};
    conv_kernel<<<B, NT>>>(x, ci, B);

    // 3) batch-major fc stack
    fcb_kernel<0><<<20480 / 4, 512>>>(B);
    fcb_kernel<1><<<10240 / 4, 512>>>(B);
    fcb_kernel<2><<<5120 / 4, 512>>>(B);

    // 4) group sum
    gsum_kernel<<<10, 512>>>(out, B);
}

// round 8
// speedup vs baseline: 1.6392x; 1.6392x over previous
#include <cuda_runtime.h>
#include <cuda_fp16.h>

// ---------------------------------------------------------------------------
// ConvDiffLogicMNIST — difflogic CNN forward, fully fused mega kernel.
// Gate algebra: out = A + B*a + C*b + D*a*b (per-gate coefs from softmax(w)).
// R7: conv1 via 16x256 LUT (binary inputs), padded smem activations (no
//     bounds checks), direct tap offsets in decoded wiring.
// ---------------------------------------------------------------------------

#define DEV_INLINE __device__ __forceinline__

static constexpr int NT = 512;   // threads per mega block

// ---- conv coefficient table offsets (float4 units) ----
static constexpr int OFF_C1_0 = 0;       // 16*4
static constexpr int OFF_C1_1 = 64;      // 16*2
static constexpr int OFF_C1_2 = 96;      // 16*1
static constexpr int OFF_C2_0 = 112;     // 48*4
static constexpr int OFF_C2_1 = 304;     // 48*2
static constexpr int OFF_C2_2 = 400;     // 48*1
static constexpr int OFF_C3_0 = 448;     // 144*4
static constexpr int OFF_C3_1 = 1024;    // 144*2
static constexpr int OFF_C3_2 = 1312;    // 144*1
static constexpr int N_CONV_COEF = 1456;

// ---- fc gate offsets (gate units) ----
static constexpr int FC1_OFF = 0;        // 20480
static constexpr int FC2_OFF = 20480;    // 10240
static constexpr int FC3_OFF = 30720;    // 5120
static constexpr int N_FC    = 35840;
static constexpr int N_GATES = 37296;

// ---- smem layout (float units) ----
static constexpr int S_LUT  = 0;                    // 16*256 = 4096
static constexpr int S_XBIN = 4096;                 // 784 (int)
static constexpr int S_ACT1 = 4880;                 // 16*14*14 = 3136 (padded)
static constexpr int S_ACT2 = 8016;                 // 48*8*8  = 3072 (padded)
static constexpr int S_ACT3 = 11088;                // 144*3*3 = 1296
static constexpr int S_FC1  = 12384;                // 20480 (reused for fc3 out)
static constexpr int S_FC2  = 32864;                // 10240
static constexpr int S_WIRE = 43104;                // 144*9 (int)
static constexpr int SMEM_BYTES = (S_WIRE + 144 * 9) * 4;   // 177600 B

// ---- fc gate metadata: one 16B record -> single LDG.128 per gate ----
struct __align__(16) FcGate {
    unsigned idx;     // ia | ib<<16
    __half2  ab;      // (A, B)
    __half2  cd;      // (C, D)
    unsigned pad;
};

// ---- device scratch ----
__device__ float4 g_coef[N_CONV_COEF];
__device__ FcGate g_fcg[N_FC];

// op -> (const, a, b, ab) coefficients for the 16 two-input soft boolean ops
__constant__ float OPC0[16]  = {0,0,0,0, 0,0,0,0, 1,1,1,1, 1,1,1,1};
__constant__ float OPCA[16]  = {0,0,1,1, 0,0,1,1, -1,-1,0,0, -1,-1,0,0};
__constant__ float OPCB[16]  = {0,0,0,0, 1,1,1,1, -1,-1,-1,-1, 0,0,0,0};
__constant__ float OPCAB[16] = {0,1,-1,0, -1,0,-2,-1, 1,2,0,1, 0,1,-1,0};

DEV_INLINE float gate_eval(float A, float Bc, float Cc, float D, float a, float b) {
    return fmaf(b, fmaf(a, D, Cc), fmaf(a, Bc, A));
}
DEV_INLINE float gate_eval4(float4 c, float a, float b) {
    return gate_eval(c.x, c.y, c.z, c.w, a, b);
}
DEV_INLINE float sel4(const float h[4], int i) {
    float r = h[0];
    r = (i == 1) ? h[1] : r;
    r = (i == 2) ? h[2] : r;
    r = (i == 3) ? h[3] : r;
    return r;
}

// ---------------------------------------------------------------------------
// Kernel 1: softmax(w) -> (A,B,C,D); conv -> g_coef fp32; fc -> 16B records.
// ---------------------------------------------------------------------------
struct CoefSeg { const float* w; const int* idx; int off; int cnt; };
struct CoefArgs { CoefSeg s[12]; };

__global__ void coef_kernel(CoefArgs args) {
    int tid = blockIdx.x * blockDim.x + threadIdx.x;
    if (tid >= N_GATES) return;
    int rem = tid, i = 0;
    while (rem >= args.s[i].cnt) { rem -= args.s[i].cnt; i++; }
    const float* w = args.s[i].w + rem * 16;

    float wv[16], m = -1e30f;
#pragma unroll
    for (int k = 0; k < 16; k++) { wv[k] = w[k]; m = fmaxf(m, wv[k]); }
    float e[16], sum = 0.f;
#pragma unroll
    for (int k = 0; k < 16; k++) { e[k] = __expf(wv[k] - m); sum += e[k]; }
    float inv = 1.f / sum;
    float A = 0.f, Bc = 0.f, Cc = 0.f, D = 0.f;
#pragma unroll
    for (int k = 0; k < 16; k++) {
        float p = e[k] * inv;
        A  = fmaf(p, OPC0[k],  A);
        Bc = fmaf(p, OPCA[k],  Bc);
        Cc = fmaf(p, OPCB[k],  Cc);
        D  = fmaf(p, OPCAB[k], D);
    }
    if (i < 9) {
        g_coef[args.s[i].off + rem] = make_float4(A, Bc, Cc, D);
    } else {
        int o = args.s[i].off + rem;
        const int* idx = args.s[i].idx;
        FcGate gte;
        gte.idx = (unsigned)idx[rem] | ((unsigned)idx[args.s[i].cnt + rem] << 16);
        gte.ab  = __floats2half2_rn(A, Bc);
        gte.cd  = __floats2half2_rn(Cc, D);
        gte.pad = 0;
        g_fcg[o] = gte;
    }
}

// ---------------------------------------------------------------------------
// Conv phase (conv2/conv3): padded smem in -> padded smem out, 2x2 maxpool.
// wire[f*9+j] = direct tap offset (c*INW*INW + ky*INW + kx); [f*9+8] = sels.
// Padded input: true position (oy,ox) with pad=1 reads at base oy*INW+ox.
// ---------------------------------------------------------------------------
template <int INW, int KS, int OH, int OUTW, int OUTB, int F, int OFF>
DEV_INLINE void conv_phase(const float* __restrict__ in_s, float* __restrict__ out_s,
                           const int* __restrict__ idx0, const int* __restrict__ idx1,
                           const int* __restrict__ idx2, int* __restrict__ wire,
                           int tid) {
    constexpr int OHP = OH / 2;
    constexpr int NOUT = F * OHP * OHP;
    constexpr int KSQ = KS * KS;

    for (int f = tid; f < F; f += NT) {
        int sel = 0;
#pragma unroll
        for (int g = 0; g < 2; g++) {
            sel |= (idx1[f * 2 + g] & 3) << (g * 2);
            sel |= (idx1[F * 2 + f * 2 + g] & 3) << (4 + g * 2);
        }
        sel |= (idx2[f] & 1) << 8;
        sel |= (idx2[F + f] & 1) << 9;
        wire[f * 9 + 8] = sel;
#pragma unroll
        for (int j = 0; j < 8; j++) {
            int p = (j < 4) ? idx0[f * 4 + j] : idx0[F * 4 + f * 4 + (j - 4)];
            int c = p / KSQ;
            int kk = p % KSQ;
            wire[f * 9 + j] = c * INW * INW + (kk / KS) * INW + (kk % KS);
        }
    }
    __syncthreads();

    for (int o = tid; o < NOUT; o += NT) {
        int px = o % OHP;
        int py = (o / OHP) % OHP;
        int f  = o / (OHP * OHP);

        int toff[8];
#pragma unroll
        for (int j = 0; j < 8; j++) toff[j] = wire[f * 9 + j];
        int sel = wire[f * 9 + 8];

        float4 c0[4], c1[2], c2;
#pragma unroll
        for (int g = 0; g < 4; g++) c0[g] = g_coef[OFF + f * 4 + g];
#pragma unroll
        for (int g = 0; g < 2; g++) c1[g] = g_coef[OFF + F * 4 + f * 2 + g];
        c2 = g_coef[OFF + F * 6 + f];

        float m = -1e30f;
#pragma unroll
        for (int dy = 0; dy < 2; dy++) {
#pragma unroll
            for (int dx = 0; dx < 2; dx++) {
                int base = (2 * py + dy) * INW + (2 * px + dx);
                float v[8];
#pragma unroll
                for (int j = 0; j < 8; j++) v[j] = in_s[toff[j] + base];
                float h0[4];
#pragma unroll
                for (int g = 0; g < 4; g++) h0[g] = gate_eval4(c0[g], v[g], v[g + 4]);
                float h1[2];
                h1[0] = gate_eval4(c1[0], sel4(h0, sel & 3), sel4(h0, (sel >> 4) & 3));
                h1[1] = gate_eval4(c1[1], sel4(h0, (sel >> 2) & 3), sel4(h0, (sel >> 6) & 3));
                float ha = ((sel >> 8) & 1) ? h1[1] : h1[0];
                float hb = ((sel >> 9) & 1) ? h1[1] : h1[0];
                m = fmaxf(m, gate_eval4(c2, ha, hb));
            }
        }
        out_s[f * OUTW * OUTW + (py + OUTB) * OUTW + (px + OUTB)] = m;
    }
    __syncthreads();
}

// ---------------------------------------------------------------------------
// FC phase: smem in -> smem out; one 16B metadata record per gate.
// ---------------------------------------------------------------------------
template <int DOUT, int GOFF>
DEV_INLINE void fc_phase(const float* __restrict__ in_s, float* __restrict__ out_s,
                         int tid) {
    const uint4* __restrict__ meta = reinterpret_cast<const uint4*>(g_fcg);
#pragma unroll 4
    for (int o = tid; o < DOUT; o += NT) {
        uint4 r = __ldg(&meta[GOFF + o]);
        float a  = in_s[r.x & 0xffffu];
        float bb = in_s[r.x >> 16];
        float2 AB = __half22float2(*reinterpret_cast<__half2*>(&r.y));
        float2 CD = __half22float2(*reinterpret_cast<__half2*>(&r.z));
        out_s[o] = gate_eval(AB.x, AB.y, CD.x, CD.y, a, bb);
    }
    __syncthreads();
}

// ---------------------------------------------------------------------------
// Kernel 2: mega — whole network per image in shared memory.
// ---------------------------------------------------------------------------
struct ConvIdx {
    const int *c1_0, *c1_1, *c1_2;
    const int *c2_0, *c2_1, *c2_2;
    const int *c3_0, *c3_1, *c3_2;
};

__global__ __launch_bounds__(NT)
void mega_kernel(const float* __restrict__ x, ConvIdx ci, float* __restrict__ out) {
    extern __shared__ float sm[];
    int* xbin = reinterpret_cast<int*>(sm + S_XBIN);
    int* wire = reinterpret_cast<int*>(sm + S_WIRE);
    float* lut = sm + S_LUT;
    const int tid = threadIdx.x;
    const int b = blockIdx.x;

    // ---- setup: zero padded act buffers, binarize, conv1 taps, conv1 LUT ----
    for (int i = tid; i < 3136; i += NT) sm[S_ACT1 + i] = 0.f;
    for (int i = tid; i < 3072; i += NT) sm[S_ACT2 + i] = 0.f;
    for (int i = tid; i < 784; i += NT)
        xbin[i] = (x[b * 784 + i] > 0.5f) ? 1 : 0;

    // conv1 tap offsets: wire[f*8+j] = ky*28 + kx  (CIN=1, KS=5, PAD=0)
    for (int t = tid; t < 16 * 8; t += NT) {
        int f = t >> 3, j = t & 7;
        int p = (j < 4) ? ci.c1_0[f * 4 + j] : ci.c1_0[64 + f * 4 + (j - 4)];
        int kk = p % 25;
        wire[t] = (p / 25) * 784 + (kk / 5) * 28 + (kk % 5);
    }

    // conv1 LUT: 16 filters x 256 binary tap patterns (bit-exact tree eval)
    for (int e = tid; e < 4096; e += NT) {
        int f = e >> 8, pat = e & 255;
        float4 c0[4], c1[2], c2;
#pragma unroll
        for (int g = 0; g < 4; g++) c0[g] = g_coef[OFF_C1_0 + f * 4 + g];
#pragma unroll
        for (int g = 0; g < 2; g++) c1[g] = g_coef[OFF_C1_1 + f * 2 + g];
        c2 = g_coef[OFF_C1_2 + f];
        float v[8];
#pragma unroll
        for (int j = 0; j < 8; j++) v[j] = (float)((pat >> j) & 1);
        float h0[4];
#pragma unroll
        for (int g = 0; g < 4; g++) h0[g] = gate_eval4(c0[g], v[g], v[g + 4]);
        float h1[2];
        h1[0] = gate_eval4(c1[0], sel4(h0, ci.c1_1[f * 2] & 3),
                           sel4(h0, ci.c1_1[32 + f * 2] & 3));
        h1[1] = gate_eval4(c1[1], sel4(h0, ci.c1_1[f * 2 + 1] & 3),
                           sel4(h0, ci.c1_1[32 + f * 2 + 1] & 3));
        float ha = (ci.c1_2[f] & 1) ? h1[1] : h1[0];
        float hb = (ci.c1_2[16 + f] & 1) ? h1[1] : h1[0];
        lut[e] = gate_eval4(c2, ha, hb);
    }
    __syncthreads();

    // ---- conv1 compute via LUT + 2x2 pool -> act1 padded (16x14x14) ----
    for (int o = tid; o < 2304; o += NT) {
        int px = o % 12;
        int py = (o / 12) % 12;
        int f  = o / 144;
        int toff[8];
#pragma unroll
        for (int j = 0; j < 8; j++) toff[j] = wire[f * 8 + j];
        const float* lf = lut + f * 256;
        float m = -1e30f;
#pragma unroll
        for (int dy = 0; dy < 2; dy++) {
#pragma unroll
            for (int dx = 0; dx < 2; dx++) {
                int base = (2 * py + dy) * 28 + (2 * px + dx);
                int pat = 0;
#pragma unroll
                for (int j = 0; j < 8; j++) pat |= xbin[toff[j] + base] << j;
                m = fmaxf(m, lf[pat]);
            }
        }
        sm[S_ACT1 + f * 196 + (py + 1) * 14 + (px + 1)] = m;
    }
    __syncthreads();

    // ---- conv2: act1 (14x14 padded) -> act2 padded (48x8x8) ----
    conv_phase<14, 3, 12, 8, 1, 48, OFF_C2_0>(sm + S_ACT1, sm + S_ACT2,
                                              ci.c2_0, ci.c2_1, ci.c2_2, wire, tid);
    // ---- conv3: act2 (8x8 padded) -> act3 (144x3x3, flatten order) ----
    conv_phase<8, 3, 6, 3, 0, 144, OFF_C3_0>(sm + S_ACT2, sm + S_ACT3,
                                             ci.c3_0, ci.c3_1, ci.c3_2, wire, tid);

    // ---- fc stack ----
    fc_phase<20480, FC1_OFF>(sm + S_ACT3, sm + S_FC1, tid);
    fc_phase<10240, FC2_OFF>(sm + S_FC1, sm + S_FC2, tid);
    fc_phase<5120, FC3_OFF>(sm + S_FC2, sm + S_FC1, tid);   // fc3 out reuses fc1 buf

    // ---- groupsum: 10 classes x 512 gates, one warp per class ----
    const float* f3 = sm + S_FC1;
    int w = tid >> 5, lane = tid & 31;
    if (w < 10) {
        float s = 0.f;
#pragma unroll
        for (int k = 0; k < 16; k++) s += f3[w * 512 + lane + 32 * k];
#pragma unroll
        for (int o = 16; o; o >>= 1) s += __shfl_xor_sync(0xffffffffu, s, o);
        if (lane == 0) out[b * 10 + w] = s * (1.f / 30.f);
    }
}

// ---------------------------------------------------------------------------
static inline int cdiv(int a, int b) { return (a + b - 1) / b; }

extern "C" void kernel_launch(void* const* d_in, const int* in_sizes, int n_in,
                              void* d_out, int out_size) {
    const float* x = (const float*)d_in[0];
    const int B = in_sizes[0] / (28 * 28);

    const int* c1_i0 = (const int*)d_in[1];
    const float* c1_w0 = (const float*)d_in[2];
    const int* c1_i1 = (const int*)d_in[3];
    const float* c1_w1 = (const float*)d_in[4];
    const int* c1_i2 = (const int*)d_in[5];
    const float* c1_w2 = (const float*)d_in[6];
    const int* c2_i0 = (const int*)d_in[7];
    const float* c2_w0 = (const float*)d_in[8];
    const int* c2_i1 = (const int*)d_in[9];
    const float* c2_w1 = (const float*)d_in[10];
    const int* c2_i2 = (const int*)d_in[11];
    const float* c2_w2 = (const float*)d_in[12];
    const int* c3_i0 = (const int*)d_in[13];
    const float* c3_w0 = (const float*)d_in[14];
    const int* c3_i1 = (const int*)d_in[15];
    const float* c3_w1 = (const float*)d_in[16];
    const int* c3_i2 = (const int*)d_in[17];
    const float* c3_w2 = (const float*)d_in[18];
    const int* fc1_i = (const int*)d_in[19];
    const float* fc1_w = (const float*)d_in[20];
    const int* fc2_i = (const int*)d_in[21];
    const float* fc2_w = (const float*)d_in[22];
    const int* fc3_i = (const int*)d_in[23];
    const float* fc3_w = (const float*)d_in[24];
    float* out = (float*)d_out;

    // 1) gate coefficients + fc metadata packing
    CoefArgs ca;
    ca.s[0]  = {c1_w0, nullptr, OFF_C1_0, 64};
    ca.s[1]  = {c1_w1, nullptr, OFF_C1_1, 32};
    ca.s[2]  = {c1_w2, nullptr, OFF_C1_2, 16};
    ca.s[3]  = {c2_w0, nullptr, OFF_C2_0, 192};
    ca.s[4]  = {c2_w1, nullptr, OFF_C2_1, 96};
    ca.s[5]  = {c2_w2, nullptr, OFF_C2_2, 48};
    ca.s[6]  = {c3_w0, nullptr, OFF_C3_0, 576};
    ca.s[7]  = {c3_w1, nullptr, OFF_C3_1, 288};
    ca.s[8]  = {c3_w2, nullptr, OFF_C3_2, 144};
    ca.s[9]  = {fc1_w, fc1_i, FC1_OFF, 20480};
    ca.s[10] = {fc2_w, fc2_i, FC2_OFF, 10240};
    ca.s[11] = {fc3_w, fc3_i, FC3_OFF, 5120};
    coef_kernel<<<cdiv(N_GATES, 256), 256>>>(ca);

    // 2) whole network, one block per image
    ConvIdx ci{c1_i0, c1_i1, c1_i2, c2_i0, c2_i1, c2_i2, c3_i0, c3_i1, c3_i2};
    cudaFuncSetAttribute(mega_kernel, cudaFuncAttributeMaxDynamicSharedMemorySize,
                         SMEM_BYTES);
    mega_kernel<<<B, NT, SMEM_BYTES>>>(x, ci, out);
}

// round 9
// speedup vs baseline: 1.8337x; 1.1187x over previous
#include <cuda_runtime.h>
#include <cuda_fp16.h>

// ---------------------------------------------------------------------------
// ConvDiffLogicMNIST — difflogic CNN forward, fully fused mega kernel.
// Gate algebra: out = A + B*a + C*b + D*a*b (per-gate coefs from softmax(w)).
// R9: NT=1024 (R8 code is lean enough to fit 64-reg cap without spills;
//     doubles resident warps on a latency-bound kernel).
// ---------------------------------------------------------------------------

#define DEV_INLINE __device__ __forceinline__

static constexpr int NT = 1024;   // threads per mega block

// ---- conv coefficient table offsets (float4 units) ----
static constexpr int OFF_C1_0 = 0;       // 16*4
static constexpr int OFF_C1_1 = 64;      // 16*2
static constexpr int OFF_C1_2 = 96;      // 16*1
static constexpr int OFF_C2_0 = 112;     // 48*4
static constexpr int OFF_C2_1 = 304;     // 48*2
static constexpr int OFF_C2_2 = 400;     // 48*1
static constexpr int OFF_C3_0 = 448;     // 144*4
static constexpr int OFF_C3_1 = 1024;    // 144*2
static constexpr int OFF_C3_2 = 1312;    // 144*1
static constexpr int N_CONV_COEF = 1456;

// ---- fc gate offsets (gate units) ----
static constexpr int FC1_OFF = 0;        // 20480
static constexpr int FC2_OFF = 20480;    // 10240
static constexpr int FC3_OFF = 30720;    // 5120
static constexpr int N_FC    = 35840;
static constexpr int N_GATES = 37296;

// ---- smem layout (float units) ----
static constexpr int S_LUT  = 0;                    // 16*256 = 4096
static constexpr int S_XBIN = 4096;                 // 784 (int)
static constexpr int S_ACT1 = 4880;                 // 16*14*14 = 3136 (padded)
static constexpr int S_ACT2 = 8016;                 // 48*8*8  = 3072 (padded)
static constexpr int S_ACT3 = 11088;                // 144*3*3 = 1296
static constexpr int S_FC1  = 12384;                // 20480 (reused for fc3 out)
static constexpr int S_FC2  = 32864;                // 10240
static constexpr int S_WIRE = 43104;                // 144*9 (int)
static constexpr int SMEM_BYTES = (S_WIRE + 144 * 9) * 4;   // 177600 B

// ---- fc gate metadata: one 16B record -> single LDG.128 per gate ----
struct __align__(16) FcGate {
    unsigned idx;     // ia | ib<<16
    __half2  ab;      // (A, B)
    __half2  cd;      // (C, D)
    unsigned pad;
};

// ---- device scratch ----
__device__ float4 g_coef[N_CONV_COEF];
__device__ FcGate g_fcg[N_FC];

// op -> (const, a, b, ab) coefficients for the 16 two-input soft boolean ops
__constant__ float OPC0[16]  = {0,0,0,0, 0,0,0,0, 1,1,1,1, 1,1,1,1};
__constant__ float OPCA[16]  = {0,0,1,1, 0,0,1,1, -1,-1,0,0, -1,-1,0,0};
__constant__ float OPCB[16]  = {0,0,0,0, 1,1,1,1, -1,-1,-1,-1, 0,0,0,0};
__constant__ float OPCAB[16] = {0,1,-1,0, -1,0,-2,-1, 1,2,0,1, 0,1,-1,0};

DEV_INLINE float gate_eval(float A, float Bc, float Cc, float D, float a, float b) {
    return fmaf(b, fmaf(a, D, Cc), fmaf(a, Bc, A));
}
DEV_INLINE float gate_eval4(float4 c, float a, float b) {
    return gate_eval(c.x, c.y, c.z, c.w, a, b);
}
DEV_INLINE float sel4(const float h[4], int i) {
    float r = h[0];
    r = (i == 1) ? h[1] : r;
    r = (i == 2) ? h[2] : r;
    r = (i == 3) ? h[3] : r;
    return r;
}

// ---------------------------------------------------------------------------
// Kernel 1: softmax(w) -> (A,B,C,D); conv -> g_coef fp32; fc -> 16B records.
// ---------------------------------------------------------------------------
struct CoefSeg { const float* w; const int* idx; int off; int cnt; };
struct CoefArgs { CoefSeg s[12]; };

__global__ void coef_kernel(CoefArgs args) {
    int tid = blockIdx.x * blockDim.x + threadIdx.x;
    if (tid >= N_GATES) return;
    int rem = tid, i = 0;
    while (rem >= args.s[i].cnt) { rem -= args.s[i].cnt; i++; }
    const float* w = args.s[i].w + rem * 16;

    float wv[16], m = -1e30f;
#pragma unroll
    for (int k = 0; k < 16; k++) { wv[k] = w[k]; m = fmaxf(m, wv[k]); }
    float e[16], sum = 0.f;
#pragma unroll
    for (int k = 0; k < 16; k++) { e[k] = __expf(wv[k] - m); sum += e[k]; }
    float inv = 1.f / sum;
    float A = 0.f, Bc = 0.f, Cc = 0.f, D = 0.f;
#pragma unroll
    for (int k = 0; k < 16; k++) {
        float p = e[k] * inv;
        A  = fmaf(p, OPC0[k],  A);
        Bc = fmaf(p, OPCA[k],  Bc);
        Cc = fmaf(p, OPCB[k],  Cc);
        D  = fmaf(p, OPCAB[k], D);
    }
    if (i < 9) {
        g_coef[args.s[i].off + rem] = make_float4(A, Bc, Cc, D);
    } else {
        int o = args.s[i].off + rem;
        const int* idx = args.s[i].idx;
        FcGate gte;
        gte.idx = (unsigned)idx[rem] | ((unsigned)idx[args.s[i].cnt + rem] << 16);
        gte.ab  = __floats2half2_rn(A, Bc);
        gte.cd  = __floats2half2_rn(Cc, D);
        gte.pad = 0;
        g_fcg[o] = gte;
    }
}

// ---------------------------------------------------------------------------
// Conv phase (conv2/conv3): padded smem in -> padded smem out, 2x2 maxpool.
// wire[f*9+j] = direct tap offset (c*INW*INW + ky*INW + kx); [f*9+8] = sels.
// ---------------------------------------------------------------------------
template <int INW, int KS, int OH, int OUTW, int OUTB, int F, int OFF>
DEV_INLINE void conv_phase(const float* __restrict__ in_s, float* __restrict__ out_s,
                           const int* __restrict__ idx0, const int* __restrict__ idx1,
                           const int* __restrict__ idx2, int* __restrict__ wire,
                           int tid) {
    constexpr int OHP = OH / 2;
    constexpr int NOUT = F * OHP * OHP;
    constexpr int KSQ = KS * KS;

    for (int f = tid; f < F; f += NT) {
        int sel = 0;
#pragma unroll
        for (int g = 0; g < 2; g++) {
            sel |= (idx1[f * 2 + g] & 3) << (g * 2);
            sel |= (idx1[F * 2 + f * 2 + g] & 3) << (4 + g * 2);
        }
        sel |= (idx2[f] & 1) << 8;
        sel |= (idx2[F + f] & 1) << 9;
        wire[f * 9 + 8] = sel;
#pragma unroll
        for (int j = 0; j < 8; j++) {
            int p = (j < 4) ? idx0[f * 4 + j] : idx0[F * 4 + f * 4 + (j - 4)];
            int c = p / KSQ;
            int kk = p % KSQ;
            wire[f * 9 + j] = c * INW * INW + (kk / KS) * INW + (kk % KS);
        }
    }
    __syncthreads();

    for (int o = tid; o < NOUT; o += NT) {
        int px = o % OHP;
        int py = (o / OHP) % OHP;
        int f  = o / (OHP * OHP);

        int toff[8];
#pragma unroll
        for (int j = 0; j < 8; j++) toff[j] = wire[f * 9 + j];
        int sel = wire[f * 9 + 8];

        float4 c0[4], c1[2], c2;
#pragma unroll
        for (int g = 0; g < 4; g++) c0[g] = g_coef[OFF + f * 4 + g];
#pragma unroll
        for (int g = 0; g < 2; g++) c1[g] = g_coef[OFF + F * 4 + f * 2 + g];
        c2 = g_coef[OFF + F * 6 + f];

        float m = -1e30f;
#pragma unroll
        for (int dy = 0; dy < 2; dy++) {
#pragma unroll
            for (int dx = 0; dx < 2; dx++) {
                int base = (2 * py + dy) * INW + (2 * px + dx);
                float v[8];
#pragma unroll
                for (int j = 0; j < 8; j++) v[j] = in_s[toff[j] + base];
                float h0[4];
#pragma unroll
                for (int g = 0; g < 4; g++) h0[g] = gate_eval4(c0[g], v[g], v[g + 4]);
                float h1[2];
                h1[0] = gate_eval4(c1[0], sel4(h0, sel & 3), sel4(h0, (sel >> 4) & 3));
                h1[1] = gate_eval4(c1[1], sel4(h0, (sel >> 2) & 3), sel4(h0, (sel >> 6) & 3));
                float ha = ((sel >> 8) & 1) ? h1[1] : h1[0];
                float hb = ((sel >> 9) & 1) ? h1[1] : h1[0];
                m = fmaxf(m, gate_eval4(c2, ha, hb));
            }
        }
        out_s[f * OUTW * OUTW + (py + OUTB) * OUTW + (px + OUTB)] = m;
    }
    __syncthreads();
}

// ---------------------------------------------------------------------------
// FC phase: smem in -> smem out; one 16B metadata record per gate.
// ---------------------------------------------------------------------------
template <int DOUT, int GOFF>
DEV_INLINE void fc_phase(const float* __restrict__ in_s, float* __restrict__ out_s,
                         int tid) {
    const uint4* __restrict__ meta = reinterpret_cast<const uint4*>(g_fcg);
#pragma unroll 4
    for (int o = tid; o < DOUT; o += NT) {
        uint4 r = __ldg(&meta[GOFF + o]);
        float a  = in_s[r.x & 0xffffu];
        float bb = in_s[r.x >> 16];
        float2 AB = __half22float2(*reinterpret_cast<__half2*>(&r.y));
        float2 CD = __half22float2(*reinterpret_cast<__half2*>(&r.z));
        out_s[o] = gate_eval(AB.x, AB.y, CD.x, CD.y, a, bb);
    }
    __syncthreads();
}

// ---------------------------------------------------------------------------
// Kernel 2: mega — whole network per image in shared memory.
// ---------------------------------------------------------------------------
struct ConvIdx {
    const int *c1_0, *c1_1, *c1_2;
    const int *c2_0, *c2_1, *c2_2;
    const int *c3_0, *c3_1, *c3_2;
};

__global__ __launch_bounds__(NT, 1)
void mega_kernel(const float* __restrict__ x, ConvIdx ci, float* __restrict__ out) {
    extern __shared__ float sm[];
    int* xbin = reinterpret_cast<int*>(sm + S_XBIN);
    int* wire = reinterpret_cast<int*>(sm + S_WIRE);
    float* lut = sm + S_LUT;
    const int tid = threadIdx.x;
    const int b = blockIdx.x;

    // ---- setup: zero padded act buffers, binarize, conv1 taps, conv1 LUT ----
    for (int i = tid; i < 3136; i += NT) sm[S_ACT1 + i] = 0.f;
    for (int i = tid; i < 3072; i += NT) sm[S_ACT2 + i] = 0.f;
    if (tid < 784)
        xbin[tid] = (x[b * 784 + tid] > 0.5f) ? 1 : 0;

    // conv1 tap offsets: wire[f*8+j]  (CIN=1, KS=5, PAD=0)
    if (tid < 16 * 8) {
        int f = tid >> 3, j = tid & 7;
        int p = (j < 4) ? ci.c1_0[f * 4 + j] : ci.c1_0[64 + f * 4 + (j - 4)];
        int kk = p % 25;
        wire[tid] = (p / 25) * 784 + (kk / 5) * 28 + (kk % 5);
    }

    // conv1 LUT: 16 filters x 256 binary tap patterns (bit-exact tree eval)
    for (int e = tid; e < 4096; e += NT) {
        int f = e >> 8, pat = e & 255;
        float4 c0[4], c1[2], c2;
#pragma unroll
        for (int g = 0; g < 4; g++) c0[g] = g_coef[OFF_C1_0 + f * 4 + g];
#pragma unroll
        for (int g = 0; g < 2; g++) c1[g] = g_coef[OFF_C1_1 + f * 2 + g];
        c2 = g_coef[OFF_C1_2 + f];
        float v[8];
#pragma unroll
        for (int j = 0; j < 8; j++) v[j] = (float)((pat >> j) & 1);
        float h0[4];
#pragma unroll
        for (int g = 0; g < 4; g++) h0[g] = gate_eval4(c0[g], v[g], v[g + 4]);
        float h1[2];
        h1[0] = gate_eval4(c1[0], sel4(h0, ci.c1_1[f * 2] & 3),
                           sel4(h0, ci.c1_1[32 + f * 2] & 3));
        h1[1] = gate_eval4(c1[1], sel4(h0, ci.c1_1[f * 2 + 1] & 3),
                           sel4(h0, ci.c1_1[32 + f * 2 + 1] & 3));
        float ha = (ci.c1_2[f] & 1) ? h1[1] : h1[0];
        float hb = (ci.c1_2[16 + f] & 1) ? h1[1] : h1[0];
        lut[e] = gate_eval4(c2, ha, hb);
    }
    __syncthreads();

    // ---- conv1 compute via LUT + 2x2 pool -> act1 padded (16x14x14) ----
    for (int o = tid; o < 2304; o += NT) {
        int px = o % 12;
        int py = (o / 12) % 12;
        int f  = o / 144;
        int toff[8];
#pragma unroll
        for (int j = 0; j < 8; j++) toff[j] = wire[f * 8 + j];
        const float* lf = lut + f * 256;
        float m = -1e30f;
#pragma unroll
        for (int dy = 0; dy < 2; dy++) {
#pragma unroll
            for (int dx = 0; dx < 2; dx++) {
                int base = (2 * py + dy) * 28 + (2 * px + dx);
                int pat = 0;
#pragma unroll
                for (int j = 0; j < 8; j++) pat |= xbin[toff[j] + base] << j;
                m = fmaxf(m, lf[pat]);
            }
        }
        sm[S_ACT1 + f * 196 + (py + 1) * 14 + (px + 1)] = m;
    }
    __syncthreads();

    // ---- conv2: act1 (14x14 padded) -> act2 padded (48x8x8) ----
    conv_phase<14, 3, 12, 8, 1, 48, OFF_C2_0>(sm + S_ACT1, sm + S_ACT2,
                                              ci.c2_0, ci.c2_1, ci.c2_2, wire, tid);
    // ---- conv3: act2 (8x8 padded) -> act3 (144x3x3, flatten order) ----
    conv_phase<8, 3, 6, 3, 0, 144, OFF_C3_0>(sm + S_ACT2, sm + S_ACT3,
                                             ci.c3_0, ci.c3_1, ci.c3_2, wire, tid);

    // ---- fc stack ----
    fc_phase<20480, FC1_OFF>(sm + S_ACT3, sm + S_FC1, tid);
    fc_phase<10240, FC2_OFF>(sm + S_FC1, sm + S_FC2, tid);
    fc_phase<5120, FC3_OFF>(sm + S_FC2, sm + S_FC1, tid);   // fc3 out reuses fc1 buf

    // ---- groupsum: 10 classes x 512 gates, one warp per class ----
    const float* f3 = sm + S_FC1;
    int w = tid >> 5, lane = tid & 31;
    if (w < 10) {
        float s = 0.f;
#pragma unroll
        for (int k = 0; k < 16; k++) s += f3[w * 512 + lane + 32 * k];
#pragma unroll
        for (int o = 16; o; o >>= 1) s += __shfl_xor_sync(0xffffffffu, s, o);
        if (lane == 0) out[b * 10 + w] = s * (1.f / 30.f);
    }
}

// ---------------------------------------------------------------------------
static inline int cdiv(int a, int b) { return (a + b - 1) / b; }

extern "C" void kernel_launch(void* const* d_in, const int* in_sizes, int n_in,
                              void* d_out, int out_size) {
    const float* x = (const float*)d_in[0];
    const int B = in_sizes[0] / (28 * 28);

    const int* c1_i0 = (const int*)d_in[1];
    const float* c1_w0 = (const float*)d_in[2];
    const int* c1_i1 = (const int*)d_in[3];
    const float* c1_w1 = (const float*)d_in[4];
    const int* c1_i2 = (const int*)d_in[5];
    const float* c1_w2 = (const float*)d_in[6];
    const int* c2_i0 = (const int*)d_in[7];
    const float* c2_w0 = (const float*)d_in[8];
    const int* c2_i1 = (const int*)d_in[9];
    const float* c2_w1 = (const float*)d_in[10];
    const int* c2_i2 = (const int*)d_in[11];
    const float* c2_w2 = (const float*)d_in[12];
    const int* c3_i0 = (const int*)d_in[13];
    const float* c3_w0 = (const float*)d_in[14];
    const int* c3_i1 = (const int*)d_in[15];
    const float* c3_w1 = (const float*)d_in[16];
    const int* c3_i2 = (const int*)d_in[17];
    const float* c3_w2 = (const float*)d_in[18];
    const int* fc1_i = (const int*)d_in[19];
    const float* fc1_w = (const float*)d_in[20];
    const int* fc2_i = (const int*)d_in[21];
    const float* fc2_w = (const float*)d_in[22];
    const int* fc3_i = (const int*)d_in[23];
    const float* fc3_w = (const float*)d_in[24];
    float* out = (float*)d_out;

    // 1) gate coefficients + fc metadata packing
    CoefArgs ca;
    ca.s[0]  = {c1_w0, nullptr, OFF_C1_0, 64};
    ca.s[1]  = {c1_w1, nullptr, OFF_C1_1, 32};
    ca.s[2]  = {c1_w2, nullptr, OFF_C1_2, 16};
    ca.s[3]  = {c2_w0, nullptr, OFF_C2_0, 192};
    ca.s[4]  = {c2_w1, nullptr, OFF_C2_1, 96};
    ca.s[5]  = {c2_w2, nullptr, OFF_C2_2, 48};
    ca.s[6]  = {c3_w0, nullptr, OFF_C3_0, 576};
    ca.s[7]  = {c3_w1, nullptr, OFF_C3_1, 288};
    ca.s[8]  = {c3_w2, nullptr, OFF_C3_2, 144};
    ca.s[9]  = {fc1_w, fc1_i, FC1_OFF, 20480};
    ca.s[10] = {fc2_w, fc2_i, FC2_OFF, 10240};
    ca.s[11] = {fc3_w, fc3_i, FC3_OFF, 5120};
    coef_kernel<<<cdiv(N_GATES, 256), 256>>>(ca);

    // 2) whole network, one block per image
    ConvIdx ci{c1_i0, c1_i1, c1_i2, c2_i0, c2_i1, c2_i2, c3_i0, c3_i1, c3_i2};
    cudaFuncSetAttribute(mega_kernel, cudaFuncAttributeMaxDynamicSharedMemorySize,
                         SMEM_BYTES);
    mega_kernel<<<B, NT, SMEM_BYTES>>>(x, ci, out);
}

// round 10
// speedup vs baseline: 1.8525x; 1.0102x over previous
#include <cuda_runtime.h>
#include <cuda_fp16.h>

// ---------------------------------------------------------------------------
// ConvDiffLogicMNIST — difflogic CNN forward, fully fused mega kernel.
// Gate algebra: out = A + B*a + C*b + D*a*b (per-gate coefs from softmax(w)).
// R10: FC stack in packed half2 (2 gates per thread-step, 3 HFMA2), half
//      activations in smem, pair-packed metadata (24B / 2 gates).
// ---------------------------------------------------------------------------

#define DEV_INLINE __device__ __forceinline__

static constexpr int NT = 1024;   // threads per mega block

// ---- conv coefficient table offsets (float4 units) ----
static constexpr int OFF_C1_0 = 0;       // 16*4
static constexpr int OFF_C1_1 = 64;      // 16*2
static constexpr int OFF_C1_2 = 96;      // 16*1
static constexpr int OFF_C2_0 = 112;     // 48*4
static constexpr int OFF_C2_1 = 304;     // 48*2
static constexpr int OFF_C2_2 = 400;     // 48*1
static constexpr int OFF_C3_0 = 448;     // 144*4
static constexpr int OFF_C3_1 = 1024;    // 144*2
static constexpr int OFF_C3_2 = 1312;    // 144*1
static constexpr int N_CONV_COEF = 1456;

// ---- fc gate offsets (gate units; all even so pairs never straddle) ----
static constexpr int FC1_OFF = 0;        // 20480
static constexpr int FC2_OFF = 20480;    // 10240
static constexpr int FC3_OFF = 30720;    // 5120
static constexpr int N_FC    = 35840;
static constexpr int N_GATES = 37296;

// ---- smem layout (float units) ----
static constexpr int S_LUT   = 0;                    // 16*256 = 4096
static constexpr int S_XBIN  = 4096;                 // 784 (int)
static constexpr int S_ACT1  = 4880;                 // 16*14*14 = 3136 (padded, f32)
static constexpr int S_ACT2  = 8016;                 // 48*8*8  = 3072 (padded, f32)
static constexpr int S_ACT3h = 11088;                // 1296 half = 648 fl
static constexpr int S_FC1h  = 11736;                // 20480 half = 10240 fl (fc3 reuses)
static constexpr int S_FC2h  = 21976;                // 10240 half = 5120 fl
static constexpr int S_WIRE  = 27096;                // 144*9 (int)
static constexpr int SMEM_BYTES = (S_WIRE + 144 * 9) * 4;   // ~113.6 KB

// ---- device scratch ----
__device__ float4 g_coef[N_CONV_COEF];
__device__ uint2  g_fci2[N_FC / 2];   // per pair: (ia0|ib0<<16, ia1|ib1<<16)
__device__ uint4  g_fcc4[N_FC / 2];   // per pair: half2 A01,B01,C01,D01

// op -> (const, a, b, ab) coefficients for the 16 two-input soft boolean ops
__constant__ float OPC0[16]  = {0,0,0,0, 0,0,0,0, 1,1,1,1, 1,1,1,1};
__constant__ float OPCA[16]  = {0,0,1,1, 0,0,1,1, -1,-1,0,0, -1,-1,0,0};
__constant__ float OPCB[16]  = {0,0,0,0, 1,1,1,1, -1,-1,-1,-1, 0,0,0,0};
__constant__ float OPCAB[16] = {0,1,-1,0, -1,0,-2,-1, 1,2,0,1, 0,1,-1,0};

DEV_INLINE float gate_eval(float A, float Bc, float Cc, float D, float a, float b) {
    return fmaf(b, fmaf(a, D, Cc), fmaf(a, Bc, A));
}
DEV_INLINE float gate_eval4(float4 c, float a, float b) {
    return gate_eval(c.x, c.y, c.z, c.w, a, b);
}
DEV_INLINE float sel4(const float h[4], int i) {
    float r = h[0];
    r = (i == 1) ? h[1] : r;
    r = (i == 2) ? h[2] : r;
    r = (i == 3) ? h[3] : r;
    return r;
}

// ---------------------------------------------------------------------------
// Kernel 1: softmax(w) -> (A,B,C,D); conv -> g_coef fp32; fc -> pair-packed
// half metadata.
// ---------------------------------------------------------------------------
struct CoefSeg { const float* w; const int* idx; int off; int cnt; };
struct CoefArgs { CoefSeg s[12]; };

__global__ void coef_kernel(CoefArgs args) {
    int tid = blockIdx.x * blockDim.x + threadIdx.x;
    if (tid >= N_GATES) return;
    int rem = tid, i = 0;
    while (rem >= args.s[i].cnt) { rem -= args.s[i].cnt; i++; }
    const float* w = args.s[i].w + rem * 16;

    float wv[16], m = -1e30f;
#pragma unroll
    for (int k = 0; k < 16; k++) { wv[k] = w[k]; m = fmaxf(m, wv[k]); }
    float e[16], sum = 0.f;
#pragma unroll
    for (int k = 0; k < 16; k++) { e[k] = __expf(wv[k] - m); sum += e[k]; }
    float inv = 1.f / sum;
    float A = 0.f, Bc = 0.f, Cc = 0.f, D = 0.f;
#pragma unroll
    for (int k = 0; k < 16; k++) {
        float p = e[k] * inv;
        A  = fmaf(p, OPC0[k],  A);
        Bc = fmaf(p, OPCA[k],  Bc);
        Cc = fmaf(p, OPCB[k],  Cc);
        D  = fmaf(p, OPCAB[k], D);
    }
    if (i < 9) {
        g_coef[args.s[i].off + rem] = make_float4(A, Bc, Cc, D);
    } else {
        int o = args.s[i].off + rem;     // global fc gate id
        int p = o >> 1, s = o & 1;
        const int* idx = args.s[i].idx;
        unsigned ia = (unsigned)idx[rem];
        unsigned ib = (unsigned)idx[args.s[i].cnt + rem];
        unsigned* iw = reinterpret_cast<unsigned*>(g_fci2);
        iw[p * 2 + s] = ia | (ib << 16);
        __half* ch = reinterpret_cast<__half*>(g_fcc4);
        ch[p * 8 + 0 + s] = __float2half(A);
        ch[p * 8 + 2 + s] = __float2half(Bc);
        ch[p * 8 + 4 + s] = __float2half(Cc);
        ch[p * 8 + 6 + s] = __float2half(D);
    }
}

// ---------------------------------------------------------------------------
// Conv phase (conv2/conv3): padded smem in -> out (f32 or half), 2x2 maxpool.
// wire[f*9+j] = direct tap offset; [f*9+8] = packed selector bits.
// ---------------------------------------------------------------------------
template <int INW, int KS, int OH, int OUTW, int OUTB, int F, int OFF, bool OUTH>
DEV_INLINE void conv_phase(const float* __restrict__ in_s, void* __restrict__ out_p,
                           const int* __restrict__ idx0, const int* __restrict__ idx1,
                           const int* __restrict__ idx2, int* __restrict__ wire,
                           int tid) {
    constexpr int OHP = OH / 2;
    constexpr int NOUT = F * OHP * OHP;
    constexpr int KSQ = KS * KS;

    for (int f = tid; f < F; f += NT) {
        int sel = 0;
#pragma unroll
        for (int g = 0; g < 2; g++) {
            sel |= (idx1[f * 2 + g] & 3) << (g * 2);
            sel |= (idx1[F * 2 + f * 2 + g] & 3) << (4 + g * 2);
        }
        sel |= (idx2[f] & 1) << 8;
        sel |= (idx2[F + f] & 1) << 9;
        wire[f * 9 + 8] = sel;
#pragma unroll
        for (int j = 0; j < 8; j++) {
            int p = (j < 4) ? idx0[f * 4 + j] : idx0[F * 4 + f * 4 + (j - 4)];
            int c = p / KSQ;
            int kk = p % KSQ;
            wire[f * 9 + j] = c * INW * INW + (kk / KS) * INW + (kk % KS);
        }
    }
    __syncthreads();

    for (int o = tid; o < NOUT; o += NT) {
        int px = o % OHP;
        int py = (o / OHP) % OHP;
        int f  = o / (OHP * OHP);

        int toff[8];
#pragma unroll
        for (int j = 0; j < 8; j++) toff[j] = wire[f * 9 + j];
        int sel = wire[f * 9 + 8];

        float4 c0[4], c1[2], c2;
#pragma unroll
        for (int g = 0; g < 4; g++) c0[g] = g_coef[OFF + f * 4 + g];
#pragma unroll
        for (int g = 0; g < 2; g++) c1[g] = g_coef[OFF + F * 4 + f * 2 + g];
        c2 = g_coef[OFF + F * 6 + f];

        float m = -1e30f;
#pragma unroll
        for (int dy = 0; dy < 2; dy++) {
#pragma unroll
            for (int dx = 0; dx < 2; dx++) {
                int base = (2 * py + dy) * INW + (2 * px + dx);
                float v[8];
#pragma unroll
                for (int j = 0; j < 8; j++) v[j] = in_s[toff[j] + base];
                float h0[4];
#pragma unroll
                for (int g = 0; g < 4; g++) h0[g] = gate_eval4(c0[g], v[g], v[g + 4]);
                float h1[2];
                h1[0] = gate_eval4(c1[0], sel4(h0, sel & 3), sel4(h0, (sel >> 4) & 3));
                h1[1] = gate_eval4(c1[1], sel4(h0, (sel >> 2) & 3), sel4(h0, (sel >> 6) & 3));
                float ha = ((sel >> 8) & 1) ? h1[1] : h1[0];
                float hb = ((sel >> 9) & 1) ? h1[1] : h1[0];
                m = fmaxf(m, gate_eval4(c2, ha, hb));
            }
        }
        int oi = f * OUTW * OUTW + (py + OUTB) * OUTW + (px + OUTB);
        if (OUTH)
            reinterpret_cast<__half*>(out_p)[oi] = __float2half(m);
        else
            reinterpret_cast<float*>(out_p)[oi] = m;
    }
    __syncthreads();
}

// ---------------------------------------------------------------------------
// FC phase (half2, 2 gates per step): smem half in -> smem half out.
// ---------------------------------------------------------------------------
template <int DOUT, int GOFF>
DEV_INLINE void fc_phase_h(const __half* __restrict__ in_s, __half* __restrict__ out_s,
                           int tid) {
    constexpr int PAIRS = DOUT / 2;
    constexpr int POFF = GOFF / 2;
#pragma unroll 4
    for (int p = tid; p < PAIRS; p += NT) {
        uint2 ri = __ldg(&g_fci2[POFF + p]);
        uint4 rc = __ldg(&g_fcc4[POFF + p]);
        __half a0 = in_s[ri.x & 0xffffu], b0 = in_s[ri.x >> 16];
        __half a1 = in_s[ri.y & 0xffffu], b1 = in_s[ri.y >> 16];
        __half2 a01 = __halves2half2(a0, a1);
        __half2 b01 = __halves2half2(b0, b1);
        __half2 A2 = *reinterpret_cast<__half2*>(&rc.x);
        __half2 B2 = *reinterpret_cast<__half2*>(&rc.y);
        __half2 C2 = *reinterpret_cast<__half2*>(&rc.z);
        __half2 D2 = *reinterpret_cast<__half2*>(&rc.w);
        __half2 o01 = __hfma2(b01, __hfma2(a01, D2, C2), __hfma2(a01, B2, A2));
        reinterpret_cast<__half2*>(out_s)[p] = o01;
    }
    __syncthreads();
}

// ---------------------------------------------------------------------------
// Kernel 2: mega — whole network per image in shared memory.
// ---------------------------------------------------------------------------
struct ConvIdx {
    const int *c1_0, *c1_1, *c1_2;
    const int *c2_0, *c2_1, *c2_2;
    const int *c3_0, *c3_1, *c3_2;
};

__global__ __launch_bounds__(NT, 1)
void mega_kernel(const float* __restrict__ x, ConvIdx ci, float* __restrict__ out) {
    extern __shared__ float sm[];
    int* xbin = reinterpret_cast<int*>(sm + S_XBIN);
    int* wire = reinterpret_cast<int*>(sm + S_WIRE);
    float* lut = sm + S_LUT;
    __half* act3h = reinterpret_cast<__half*>(sm + S_ACT3h);
    __half* fc1h  = reinterpret_cast<__half*>(sm + S_FC1h);
    __half* fc2h  = reinterpret_cast<__half*>(sm + S_FC2h);
    const int tid = threadIdx.x;
    const int b = blockIdx.x;

    // ---- setup: zero padded act buffers, binarize, conv1 taps, conv1 LUT ----
    for (int i = tid; i < 3136; i += NT) sm[S_ACT1 + i] = 0.f;
    for (int i = tid; i < 3072; i += NT) sm[S_ACT2 + i] = 0.f;
    if (tid < 784)
        xbin[tid] = (x[b * 784 + tid] > 0.5f) ? 1 : 0;

    // conv1 tap offsets (CIN=1, KS=5, PAD=0)
    if (tid < 16 * 8) {
        int f = tid >> 3, j = tid & 7;
        int p = (j < 4) ? ci.c1_0[f * 4 + j] : ci.c1_0[64 + f * 4 + (j - 4)];
        int kk = p % 25;
        wire[tid] = (p / 25) * 784 + (kk / 5) * 28 + (kk % 5);
    }

    // conv1 LUT: 16 filters x 256 binary tap patterns (bit-exact tree eval)
    for (int e = tid; e < 4096; e += NT) {
        int f = e >> 8, pat = e & 255;
        float4 c0[4], c1[2], c2;
#pragma unroll
        for (int g = 0; g < 4; g++) c0[g] = g_coef[OFF_C1_0 + f * 4 + g];
#pragma unroll
        for (int g = 0; g < 2; g++) c1[g] = g_coef[OFF_C1_1 + f * 2 + g];
        c2 = g_coef[OFF_C1_2 + f];
        float v[8];
#pragma unroll
        for (int j = 0; j < 8; j++) v[j] = (float)((pat >> j) & 1);
        float h0[4];
#pragma unroll
        for (int g = 0; g < 4; g++) h0[g] = gate_eval4(c0[g], v[g], v[g + 4]);
        float h1[2];
        h1[0] = gate_eval4(c1[0], sel4(h0, ci.c1_1[f * 2] & 3),
                           sel4(h0, ci.c1_1[32 + f * 2] & 3));
        h1[1] = gate_eval4(c1[1], sel4(h0, ci.c1_1[f * 2 + 1] & 3),
                           sel4(h0, ci.c1_1[32 + f * 2 + 1] & 3));
        float ha = (ci.c1_2[f] & 1) ? h1[1] : h1[0];
        float hb = (ci.c1_2[16 + f] & 1) ? h1[1] : h1[0];
        lut[e] = gate_eval4(c2, ha, hb);
    }
    __syncthreads();

    // ---- conv1 via LUT + 2x2 pool -> act1 padded (16x14x14, f32) ----
    for (int o = tid; o < 2304; o += NT) {
        int px = o % 12;
        int py = (o / 12) % 12;
        int f  = o / 144;
        int toff[8];
#pragma unroll
        for (int j = 0; j < 8; j++) toff[j] = wire[f * 8 + j];
        const float* lf = lut + f * 256;
        float m = -1e30f;
#pragma unroll
        for (int dy = 0; dy < 2; dy++) {
#pragma unroll
            for (int dx = 0; dx < 2; dx++) {
                int base = (2 * py + dy) * 28 + (2 * px + dx);
                int pat = 0;
#pragma unroll
                for (int j = 0; j < 8; j++) pat |= xbin[toff[j] + base] << j;
                m = fmaxf(m, lf[pat]);
            }
        }
        sm[S_ACT1 + f * 196 + (py + 1) * 14 + (px + 1)] = m;
    }
    __syncthreads();

    // ---- conv2: act1 (14x14 padded) -> act2 padded (48x8x8, f32) ----
    conv_phase<14, 3, 12, 8, 1, 48, OFF_C2_0, false>(
        sm + S_ACT1, sm + S_ACT2, ci.c2_0, ci.c2_1, ci.c2_2, wire, tid);
    // ---- conv3: act2 (8x8 padded) -> act3 (144x3x3, half) ----
    conv_phase<8, 3, 6, 3, 0, 144, OFF_C3_0, true>(
        sm + S_ACT2, act3h, ci.c3_0, ci.c3_1, ci.c3_2, wire, tid);

    // ---- fc stack (half2 packed) ----
    fc_phase_h<20480, FC1_OFF>(act3h, fc1h, tid);
    fc_phase_h<10240, FC2_OFF>(fc1h, fc2h, tid);
    fc_phase_h<5120, FC3_OFF>(fc2h, fc1h, tid);   // fc3 out reuses fc1 buf

    // ---- groupsum: 10 classes x 512 gates (256 half2), one warp per class ----
    const __half2* f3 = reinterpret_cast<const __half2*>(fc1h);
    int w = tid >> 5, lane = tid & 31;
    if (w < 10) {
        float s = 0.f;
#pragma unroll
        for (int k = 0; k < 8; k++) {
            float2 t = __half22float2(f3[w * 256 + lane + 32 * k]);
            s += t.x + t.y;
        }
#pragma unroll
        for (int o = 16; o; o >>= 1) s += __shfl_xor_sync(0xffffffffu, s, o);
        if (lane == 0) out[b * 10 + w] = s * (1.f / 30.f);
    }
}

// ---------------------------------------------------------------------------
static inline int cdiv(int a, int b) { return (a + b - 1) / b; }

extern "C" void kernel_launch(void* const* d_in, const int* in_sizes, int n_in,
                              void* d_out, int out_size) {
    const float* x = (const float*)d_in[0];
    const int B = in_sizes[0] / (28 * 28);

    const int* c1_i0 = (const int*)d_in[1];
    const float* c1_w0 = (const float*)d_in[2];
    const int* c1_i1 = (const int*)d_in[3];
    const float* c1_w1 = (const float*)d_in[4];
    const int* c1_i2 = (const int*)d_in[5];
    const float* c1_w2 = (const float*)d_in[6];
    const int* c2_i0 = (const int*)d_in[7];
    const float* c2_w0 = (const float*)d_in[8];
    const int* c2_i1 = (const int*)d_in[9];
    const float* c2_w1 = (const float*)d_in[10];
    const int* c2_i2 = (const int*)d_in[11];
    const float* c2_w2 = (const float*)d_in[12];
    const int* c3_i0 = (const int*)d_in[13];
    const float* c3_w0 = (const float*)d_in[14];
    const int* c3_i1 = (const int*)d_in[15];
    const float* c3_w1 = (const float*)d_in[16];
    const int* c3_i2 = (const int*)d_in[17];
    const float* c3_w2 = (const float*)d_in[18];
    const int* fc1_i = (const int*)d_in[19];
    const float* fc1_w = (const float*)d_in[20];
    const int* fc2_i = (const int*)d_in[21];
    const float* fc2_w = (const float*)d_in[22];
    const int* fc3_i = (const int*)d_in[23];
    const float* fc3_w = (const float*)d_in[24];
    float* out = (float*)d_out;

    // 1) gate coefficients + fc metadata packing
    CoefArgs ca;
    ca.s[0]  = {c1_w0, nullptr, OFF_C1_0, 64};
    ca.s[1]  = {c1_w1, nullptr, OFF_C1_1, 32};
    ca.s[2]  = {c1_w2, nullptr, OFF_C1_2, 16};
    ca.s[3]  = {c2_w0, nullptr, OFF_C2_0, 192};
    ca.s[4]  = {c2_w1, nullptr, OFF_C2_1, 96};
    ca.s[5]  = {c2_w2, nullptr, OFF_C2_2, 48};
    ca.s[6]  = {c3_w0, nullptr, OFF_C3_0, 576};
    ca.s[7]  = {c3_w1, nullptr, OFF_C3_1, 288};
    ca.s[8]  = {c3_w2, nullptr, OFF_C3_2, 144};
    ca.s[9]  = {fc1_w, fc1_i, FC1_OFF, 20480};
    ca.s[10] = {fc2_w, fc2_i, FC2_OFF, 10240};
    ca.s[11] = {fc3_w, fc3_i, FC3_OFF, 5120};
    coef_kernel<<<cdiv(N_GATES, 256), 256>>>(ca);

    // 2) whole network, one block per image
    ConvIdx ci{c1_i0, c1_i1, c1_i2, c2_i0, c2_i1, c2_i2, c3_i0, c3_i1, c3_i2};
    cudaFuncSetAttribute(mega_kernel, cudaFuncAttributeMaxDynamicSharedMemorySize,
                         SMEM_BYTES);
    mega_kernel<<<B, NT, SMEM_BYTES>>>(x, ci, out);
}

// round 11
// speedup vs baseline: 1.8544x; 1.0010x over previous
#include <cuda_runtime.h>
#include <cuda_fp16.h>

// ---------------------------------------------------------------------------
// ConvDiffLogicMNIST — difflogic CNN forward, fully fused mega kernel.
// Gate algebra: out = A + B*a + C*b + D*a*b (per-gate coefs from softmax(w)).
// R11: all per-parameter preprocessing (conv1 LUT, wiring decode) hoisted into
//      the coef kernel; mega kernel only does per-image work.
// ---------------------------------------------------------------------------

#define DEV_INLINE __device__ __forceinline__

static constexpr int NT = 1024;   // threads per mega block

// ---- conv coefficient table offsets (float4 units) ----
static constexpr int OFF_C1_0 = 0;       // 16*4
static constexpr int OFF_C1_1 = 64;      // 16*2
static constexpr int OFF_C1_2 = 96;      // 16*1
static constexpr int OFF_C2_0 = 112;     // 48*4
static constexpr int OFF_C2_1 = 304;     // 48*2
static constexpr int OFF_C2_2 = 400;     // 48*1
static constexpr int OFF_C3_0 = 448;     // 144*4
static constexpr int OFF_C3_1 = 1024;    // 144*2
static constexpr int OFF_C3_2 = 1312;    // 144*1
static constexpr int N_CONV_COEF = 1456;

// ---- fc gate offsets (gate units; all even so pairs never straddle) ----
static constexpr int FC1_OFF = 0;        // 20480
static constexpr int FC2_OFF = 20480;    // 10240
static constexpr int FC3_OFF = 30720;    // 5120
static constexpr int N_FC    = 35840;
static constexpr int N_GATES = 37296;

// ---- smem layout (float units) ----
static constexpr int S_LUT   = 0;                    // 16*256 = 4096
static constexpr int S_XBIN  = 4096;                 // 784 (int)
static constexpr int S_ACT1  = 4880;                 // 16*14*14 = 3136 (padded, f32)
static constexpr int S_ACT2  = 8016;                 // 48*8*8  = 3072 (padded, f32)
static constexpr int S_ACT3h = 11088;                // 1296 half = 648 fl
static constexpr int S_FC1h  = 11736;                // 20480 half = 10240 fl (fc3 reuses)
static constexpr int S_FC2h  = 21976;                // 10240 half = 5120 fl
static constexpr int S_WIRE  = 27096;                // 144*9 (int)
static constexpr int SMEM_BYTES = (S_WIRE + 144 * 9) * 4;   // ~113.6 KB

// ---- device scratch ----
__device__ float4 g_coef[N_CONV_COEF];
__device__ uint2  g_fci2[N_FC / 2];   // per pair: (ia0|ib0<<16, ia1|ib1<<16)
__device__ uint4  g_fcc4[N_FC / 2];   // per pair: half2 A01,B01,C01,D01
__device__ float  g_lut[4096];        // conv1 16x256 LUT
__device__ int    g_wire1[128];       // conv1 taps (16 filters x 8)
__device__ int    g_wire2[48 * 9];    // conv2 decoded wiring
__device__ int    g_wire3[144 * 9];   // conv3 decoded wiring

// op -> (const, a, b, ab) coefficients for the 16 two-input soft boolean ops
__constant__ float OPC0[16]  = {0,0,0,0, 0,0,0,0, 1,1,1,1, 1,1,1,1};
__constant__ float OPCA[16]  = {0,0,1,1, 0,0,1,1, -1,-1,0,0, -1,-1,0,0};
__constant__ float OPCB[16]  = {0,0,0,0, 1,1,1,1, -1,-1,-1,-1, 0,0,0,0};
__constant__ float OPCAB[16] = {0,1,-1,0, -1,0,-2,-1, 1,2,0,1, 0,1,-1,0};

DEV_INLINE float gate_eval(float A, float Bc, float Cc, float D, float a, float b) {
    return fmaf(b, fmaf(a, D, Cc), fmaf(a, Bc, A));
}
DEV_INLINE float gate_eval4(float4 c, float a, float b) {
    return gate_eval(c.x, c.y, c.z, c.w, a, b);
}
DEV_INLINE float sel4(const float h[4], int i) {
    float r = h[0];
    r = (i == 1) ? h[1] : r;
    r = (i == 2) ? h[2] : r;
    r = (i == 3) ? h[3] : r;
    return r;
}

// decode one conv filter's wiring into wire[f*9 .. f*9+8]
DEV_INLINE void decode_wire(int f, int F, int INW, int KS,
                            const int* idx0, const int* idx1, const int* idx2,
                            int* wire) {
    int KSQ = KS * KS;
    int sel = 0;
#pragma unroll
    for (int g = 0; g < 2; g++) {
        sel |= (idx1[f * 2 + g] & 3) << (g * 2);
        sel |= (idx1[F * 2 + f * 2 + g] & 3) << (4 + g * 2);
    }
    sel |= (idx2[f] & 1) << 8;
    sel |= (idx2[F + f] & 1) << 9;
    wire[f * 9 + 8] = sel;
#pragma unroll
    for (int j = 0; j < 8; j++) {
        int p = (j < 4) ? idx0[f * 4 + j] : idx0[F * 4 + f * 4 + (j - 4)];
        int c = p / KSQ;
        int kk = p % KSQ;
        wire[f * 9 + j] = c * INW * INW + (kk / KS) * INW + (kk % KS);
    }
}

// ---------------------------------------------------------------------------
// Kernel 1: softmax(w) -> coefs; fc -> pair-packed half metadata.
// Block 0 additionally builds the conv1 LUT (from smem-staged conv1 coefs);
// block 1 decodes all conv wiring. 256 threads/block.
// ---------------------------------------------------------------------------
struct CoefSeg { const float* w; const int* idx; int off; int cnt; };
struct CoefArgs { CoefSeg s[12]; };

__global__ void coef_kernel(CoefArgs args) {
    __shared__ float4 sc[112];   // conv1 gate coefs (block 0 only)
    int tid = threadIdx.x;
    int gid = blockIdx.x * 256 + tid;

    if (gid < N_GATES) {
        int rem = gid, i = 0;
        while (rem >= args.s[i].cnt) { rem -= args.s[i].cnt; i++; }
        const float* w = args.s[i].w + rem * 16;

        float wv[16], m = -1e30f;
#pragma unroll
        for (int k = 0; k < 16; k++) { wv[k] = w[k]; m = fmaxf(m, wv[k]); }
        float e[16], sum = 0.f;
#pragma unroll
        for (int k = 0; k < 16; k++) { e[k] = __expf(wv[k] - m); sum += e[k]; }
        float inv = 1.f / sum;
        float A = 0.f, Bc = 0.f, Cc = 0.f, D = 0.f;
#pragma unroll
        for (int k = 0; k < 16; k++) {
            float p = e[k] * inv;
            A  = fmaf(p, OPC0[k],  A);
            Bc = fmaf(p, OPCA[k],  Bc);
            Cc = fmaf(p, OPCB[k],  Cc);
            D  = fmaf(p, OPCAB[k], D);
        }
        if (i < 9) {
            g_coef[args.s[i].off + rem] = make_float4(A, Bc, Cc, D);
            if (blockIdx.x == 0 && gid < 112)
                sc[gid] = make_float4(A, Bc, Cc, D);
        } else {
            int o = args.s[i].off + rem;     // global fc gate id
            int p = o >> 1, s = o & 1;
            const int* idx = args.s[i].idx;
            unsigned ia = (unsigned)idx[rem];
            unsigned ib = (unsigned)idx[args.s[i].cnt + rem];
            unsigned* iw = reinterpret_cast<unsigned*>(g_fci2);
            iw[p * 2 + s] = ia | (ib << 16);
            __half* ch = reinterpret_cast<__half*>(g_fcc4);
            ch[p * 8 + 0 + s] = __float2half(A);
            ch[p * 8 + 2 + s] = __float2half(Bc);
            ch[p * 8 + 4 + s] = __float2half(Cc);
            ch[p * 8 + 6 + s] = __float2half(D);
        }
    }

    if (blockIdx.x == 0) {
        // build conv1 LUT from staged coefs (gates 0..111 all live in block 0)
        __syncthreads();
        const int* i1 = args.s[1].idx;   // c1_idx1
        const int* i2 = args.s[2].idx;   // c1_idx2
        for (int e = tid; e < 4096; e += 256) {
            int f = e >> 8, pat = e & 255;
            float v[8];
#pragma unroll
            for (int j = 0; j < 8; j++) v[j] = (float)((pat >> j) & 1);
            float h0[4];
#pragma unroll
            for (int g = 0; g < 4; g++)
                h0[g] = gate_eval4(sc[f * 4 + g], v[g], v[g + 4]);
            float h1[2];
            h1[0] = gate_eval4(sc[64 + f * 2],
                               sel4(h0, i1[f * 2] & 3), sel4(h0, i1[32 + f * 2] & 3));
            h1[1] = gate_eval4(sc[64 + f * 2 + 1],
                               sel4(h0, i1[f * 2 + 1] & 3), sel4(h0, i1[32 + f * 2 + 1] & 3));
            float ha = (i2[f] & 1) ? h1[1] : h1[0];
            float hb = (i2[16 + f] & 1) ? h1[1] : h1[0];
            g_lut[e] = gate_eval4(sc[96 + f], ha, hb);
        }
    } else if (blockIdx.x == 1) {
        // decode all conv wiring (pure index math, no coef dependency)
        if (tid < 48)
            decode_wire(tid, 48, 14, 3, args.s[3].idx, args.s[4].idx, args.s[5].idx,
                        g_wire2);
        else if (tid < 192)
            decode_wire(tid - 48, 144, 8, 3, args.s[6].idx, args.s[7].idx,
                        args.s[8].idx, g_wire3);
        else if (tid < 208) {
            int f = tid - 192;
            const int* idx0 = args.s[0].idx;   // c1_idx0
#pragma unroll
            for (int j = 0; j < 8; j++) {
                int p = (j < 4) ? idx0[f * 4 + j] : idx0[64 + f * 4 + (j - 4)];
                int kk = p % 25;
                g_wire1[f * 8 + j] = (p / 25) * 784 + (kk / 5) * 28 + (kk % 5);
            }
        }
    }
}

// ---------------------------------------------------------------------------
// Conv phase (conv2/conv3): padded smem in -> out (f32 or half), 2x2 maxpool.
// Wiring copied from precomputed global arrays into smem.
// ---------------------------------------------------------------------------
template <int INW, int OH, int OUTW, int OUTB, int F, int OFF, bool OUTH>
DEV_INLINE void conv_phase(const float* __restrict__ in_s, void* __restrict__ out_p,
                           const int* __restrict__ gwire, int* __restrict__ wire,
                           int tid) {
    constexpr int OHP = OH / 2;
    constexpr int NOUT = F * OHP * OHP;

    for (int i = tid; i < F * 9; i += NT) wire[i] = gwire[i];
    __syncthreads();

    for (int o = tid; o < NOUT; o += NT) {
        int px = o % OHP;
        int py = (o / OHP) % OHP;
        int f  = o / (OHP * OHP);

        int toff[8];
#pragma unroll
        for (int j = 0; j < 8; j++) toff[j] = wire[f * 9 + j];
        int sel = wire[f * 9 + 8];

        float4 c0[4], c1[2], c2;
#pragma unroll
        for (int g = 0; g < 4; g++) c0[g] = g_coef[OFF + f * 4 + g];
#pragma unroll
        for (int g = 0; g < 2; g++) c1[g] = g_coef[OFF + F * 4 + f * 2 + g];
        c2 = g_coef[OFF + F * 6 + f];

        float m = -1e30f;
#pragma unroll
        for (int dy = 0; dy < 2; dy++) {
#pragma unroll
            for (int dx = 0; dx < 2; dx++) {
                int base = (2 * py + dy) * INW + (2 * px + dx);
                float v[8];
#pragma unroll
                for (int j = 0; j < 8; j++) v[j] = in_s[toff[j] + base];
                float h0[4];
#pragma unroll
                for (int g = 0; g < 4; g++) h0[g] = gate_eval4(c0[g], v[g], v[g + 4]);
                float h1[2];
                h1[0] = gate_eval4(c1[0], sel4(h0, sel & 3), sel4(h0, (sel >> 4) & 3));
                h1[1] = gate_eval4(c1[1], sel4(h0, (sel >> 2) & 3), sel4(h0, (sel >> 6) & 3));
                float ha = ((sel >> 8) & 1) ? h1[1] : h1[0];
                float hb = ((sel >> 9) & 1) ? h1[1] : h1[0];
                m = fmaxf(m, gate_eval4(c2, ha, hb));
            }
        }
        int oi = f * OUTW * OUTW + (py + OUTB) * OUTW + (px + OUTB);
        if (OUTH)
            reinterpret_cast<__half*>(out_p)[oi] = __float2half(m);
        else
            reinterpret_cast<float*>(out_p)[oi] = m;
    }
    __syncthreads();
}

// ---------------------------------------------------------------------------
// FC phase (half2, 2 gates per step): smem half in -> smem half out.
// ---------------------------------------------------------------------------
template <int DOUT, int GOFF>
DEV_INLINE void fc_phase_h(const __half* __restrict__ in_s, __half* __restrict__ out_s,
                           int tid) {
    constexpr int PAIRS = DOUT / 2;
    constexpr int POFF = GOFF / 2;
#pragma unroll 4
    for (int p = tid; p < PAIRS; p += NT) {
        uint2 ri = __ldg(&g_fci2[POFF + p]);
        uint4 rc = __ldg(&g_fcc4[POFF + p]);
        __half a0 = in_s[ri.x & 0xffffu], b0 = in_s[ri.x >> 16];
        __half a1 = in_s[ri.y & 0xffffu], b1 = in_s[ri.y >> 16];
        __half2 a01 = __halves2half2(a0, a1);
        __half2 b01 = __halves2half2(b0, b1);
        __half2 A2 = *reinterpret_cast<__half2*>(&rc.x);
        __half2 B2 = *reinterpret_cast<__half2*>(&rc.y);
        __half2 C2 = *reinterpret_cast<__half2*>(&rc.z);
        __half2 D2 = *reinterpret_cast<__half2*>(&rc.w);
        __half2 o01 = __hfma2(b01, __hfma2(a01, D2, C2), __hfma2(a01, B2, A2));
        reinterpret_cast<__half2*>(out_s)[p] = o01;
    }
    __syncthreads();
}

// ---------------------------------------------------------------------------
// Kernel 2: mega — whole network per image in shared memory (per-image only).
// ---------------------------------------------------------------------------
__global__ __launch_bounds__(NT, 1)
void mega_kernel(const float* __restrict__ x, float* __restrict__ out) {
    extern __shared__ float sm[];
    int* xbin = reinterpret_cast<int*>(sm + S_XBIN);
    int* wire = reinterpret_cast<int*>(sm + S_WIRE);
    float* lut = sm + S_LUT;
    __half* act3h = reinterpret_cast<__half*>(sm + S_ACT3h);
    __half* fc1h  = reinterpret_cast<__half*>(sm + S_FC1h);
    __half* fc2h  = reinterpret_cast<__half*>(sm + S_FC2h);
    const int tid = threadIdx.x;
    const int b = blockIdx.x;

    // ---- setup: zero padded act buffers, binarize, copy LUT + conv1 taps ----
    for (int i = tid; i < 3136; i += NT) sm[S_ACT1 + i] = 0.f;
    for (int i = tid; i < 3072; i += NT) sm[S_ACT2 + i] = 0.f;
    if (tid < 784)
        xbin[tid] = (x[b * 784 + tid] > 0.5f) ? 1 : 0;
    for (int i = tid; i < 4096; i += NT) lut[i] = g_lut[i];
    if (tid < 128) wire[tid] = g_wire1[tid];
    __syncthreads();

    // ---- conv1 via LUT + 2x2 pool -> act1 padded (16x14x14, f32) ----
    for (int o = tid; o < 2304; o += NT) {
        int px = o % 12;
        int py = (o / 12) % 12;
        int f  = o / 144;
        int toff[8];
#pragma unroll
        for (int j = 0; j < 8; j++) toff[j] = wire[f * 8 + j];
        const float* lf = lut + f * 256;
        float m = -1e30f;
#pragma unroll
        for (int dy = 0; dy < 2; dy++) {
#pragma unroll
            for (int dx = 0; dx < 2; dx++) {
                int base = (2 * py + dy) * 28 + (2 * px + dx);
                int pat = 0;
#pragma unroll
                for (int j = 0; j < 8; j++) pat |= xbin[toff[j] + base] << j;
                m = fmaxf(m, lf[pat]);
            }
        }
        sm[S_ACT1 + f * 196 + (py + 1) * 14 + (px + 1)] = m;
    }
    __syncthreads();

    // ---- conv2: act1 (14x14 padded) -> act2 padded (48x8x8, f32) ----
    conv_phase<14, 12, 8, 1, 48, OFF_C2_0, false>(
        sm + S_ACT1, sm + S_ACT2, g_wire2, wire, tid);
    // ---- conv3: act2 (8x8 padded) -> act3 (144x3x3, half) ----
    conv_phase<8, 6, 3, 0, 144, OFF_C3_0, true>(
        sm + S_ACT2, act3h, g_wire3, wire, tid);

    // ---- fc stack (half2 packed) ----
    fc_phase_h<20480, FC1_OFF>(act3h, fc1h, tid);
    fc_phase_h<10240, FC2_OFF>(fc1h, fc2h, tid);
    fc_phase_h<5120, FC3_OFF>(fc2h, fc1h, tid);   // fc3 out reuses fc1 buf

    // ---- groupsum: 10 classes x 512 gates (256 half2), one warp per class ----
    const __half2* f3 = reinterpret_cast<const __half2*>(fc1h);
    int w = tid >> 5, lane = tid & 31;
    if (w < 10) {
        float s = 0.f;
#pragma unroll
        for (int k = 0; k < 8; k++) {
            float2 t = __half22float2(f3[w * 256 + lane + 32 * k]);
            s += t.x + t.y;
        }
#pragma unroll
        for (int o = 16; o; o >>= 1) s += __shfl_xor_sync(0xffffffffu, s, o);
        if (lane == 0) out[b * 10 + w] = s * (1.f / 30.f);
    }
}

// ---------------------------------------------------------------------------
static inline int cdiv(int a, int b) { return (a + b - 1) / b; }

extern "C" void kernel_launch(void* const* d_in, const int* in_sizes, int n_in,
                              void* d_out, int out_size) {
    const float* x = (const float*)d_in[0];
    const int B = in_sizes[0] / (28 * 28);

    const int* c1_i0 = (const int*)d_in[1];
    const float* c1_w0 = (const float*)d_in[2];
    const int* c1_i1 = (const int*)d_in[3];
    const float* c1_w1 = (const float*)d_in[4];
    const int* c1_i2 = (const int*)d_in[5];
    const float* c1_w2 = (const float*)d_in[6];
    const int* c2_i0 = (const int*)d_in[7];
    const float* c2_w0 = (const float*)d_in[8];
    const int* c2_i1 = (const int*)d_in[9];
    const float* c2_w1 = (const float*)d_in[10];
    const int* c2_i2 = (const int*)d_in[11];
    const float* c2_w2 = (const float*)d_in[12];
    const int* c3_i0 = (const int*)d_in[13];
    const float* c3_w0 = (const float*)d_in[14];
    const int* c3_i1 = (const int*)d_in[15];
    const float* c3_w1 = (const float*)d_in[16];
    const int* c3_i2 = (const int*)d_in[17];
    const float* c3_w2 = (const float*)d_in[18];
    const int* fc1_i = (const int*)d_in[19];
    const float* fc1_w = (const float*)d_in[20];
    const int* fc2_i = (const int*)d_in[21];
    const float* fc2_w = (const float*)d_in[22];
    const int* fc3_i = (const int*)d_in[23];
    const float* fc3_w = (const float*)d_in[24];
    float* out = (float*)d_out;

    // 1) gate coefficients + fc metadata + LUT + wiring (all preprocessing)
    CoefArgs ca;
    ca.s[0]  = {c1_w0, c1_i0, OFF_C1_0, 64};
    ca.s[1]  = {c1_w1, c1_i1, OFF_C1_1, 32};
    ca.s[2]  = {c1_w2, c1_i2, OFF_C1_2, 16};
    ca.s[3]  = {c2_w0, c2_i0, OFF_C2_0, 192};
    ca.s[4]  = {c2_w1, c2_i1, OFF_C2_1, 96};
    ca.s[5]  = {c2_w2, c2_i2, OFF_C2_2, 48};
    ca.s[6]  = {c3_w0, c3_i0, OFF_C3_0, 576};
    ca.s[7]  = {c3_w1, c3_i1, OFF_C3_1, 288};
    ca.s[8]  = {c3_w2, c3_i2, OFF_C3_2, 144};
    ca.s[9]  = {fc1_w, fc1_i, FC1_OFF, 20480};
    ca.s[10] = {fc2_w, fc2_i, FC2_OFF, 10240};
    ca.s[11] = {fc3_w, fc3_i, FC3_OFF, 5120};
    coef_kernel<<<cdiv(N_GATES, 256), 256>>>(ca);

    // 2) whole network, one block per image
    cudaFuncSetAttribute(mega_kernel, cudaFuncAttributeMaxDynamicSharedMemorySize,
                         SMEM_BYTES);
    mega_kernel<<<B, NT, SMEM_BYTES>>>(x, out);
}